// round 13
// baseline (speedup 1.0000x reference)
#include <cuda_runtime.h>
#include <math.h>

#define N_PCD 5000
#define N_RGB 15000
#define NTOT  20000
#define NA    4096
#define SA_NS 32
#define NB_K  64
#define K1    163
#define NROWS (NA*SA_NS)
#define NCELL 512
#define CELL_R 0.10830f   /* > sqrt(3)/16 = 0.108253: conservative half-diagonal */

// ---------------- static device scratch ----------------
__device__ float g_xs[NTOT], g_ys[NTOT], g_zs[NTOT];
__device__ float g_ax[NA], g_ay[NA], g_az[NA];
__device__ int   g_nb[NA*SA_NS];
__device__ float g_rgbT[(size_t)N_RGB*128];
__device__ float g_W1T[K1*128];
__device__ float g_W2T[128*128];
__device__ float g_W3T[128*128];
__device__ float g_fpW1T[160*128];
__device__ float g_fpW2T[128*32];
__device__ float g_G [(size_t)NROWS*K1];
__device__ float g_H1[(size_t)NROWS*128];
__device__ float g_H2[(size_t)NROWS*128];
__device__ float g_saf[NA*128];
__device__ int   g_nn[N_PCD*3];
__device__ float g_wg[N_PCD*3];
__device__ float g_fpf[N_PCD*32];
__device__ int   g_nb2[N_PCD*NB_K];
__device__ unsigned int g_gmax;
// FPS cell structures
__device__ float4 g_sp[NTOT];          // sorted (x,y,z,orig-as-float-bits)
__device__ int    g_cid[NTOT];
__device__ int    g_ccnt[NCELL];
__device__ int    g_cstart[NCELL+1];
__device__ int    g_cfill[NCELL];

// (dx*dx + dy*dy) + dz*dz, contraction forbidden (FMA could flip argmax/top-k ties)
__device__ __forceinline__ float sqdist(float ax, float ay, float az,
                                        float bx, float by, float bz) {
  float dx = __fadd_rn(ax, -bx);
  float dy = __fadd_rn(ay, -by);
  float dz = __fadd_rn(az, -bz);
  return __fadd_rn(__fadd_rn(__fmul_rn(dx,dx), __fmul_rn(dy,dy)), __fmul_rn(dz,dz));
}

__device__ __forceinline__ int cell_of(float x, float y, float z) {
  int ix = min(7, max(0, (int)(x * 8.0f)));
  int iy = min(7, max(0, (int)(y * 8.0f)));
  int iz = min(7, max(0, (int)(z * 8.0f)));
  return (iz*8 + iy)*8 + ix;
}

// ---------------- prep: SoA xyz + cell id + counts, seed FPS step 0 ----------------
__global__ void k_build(const float* __restrict__ pcd_xyz,
                        const float* __restrict__ rgb_xyz) {
  int i = blockIdx.x*blockDim.x + threadIdx.x;
  if (i == 0) {
    g_gmax = 0u;
    g_ax[0] = pcd_xyz[0]; g_ay[0] = pcd_xyz[1]; g_az[0] = pcd_xyz[2];
  }
  if (i >= NTOT) return;
  float x, y, z;
  if (i < N_PCD) { x=pcd_xyz[i*3]; y=pcd_xyz[i*3+1]; z=pcd_xyz[i*3+2]; }
  else           { int j=i-N_PCD; x=rgb_xyz[j*3]; y=rgb_xyz[j*3+1]; z=rgb_xyz[j*3+2]; }
  g_xs[i]=x; g_ys[i]=y; g_zs[i]=z;
  int c = cell_of(x, y, z);
  g_cid[i] = c;
  atomicAdd(&g_ccnt[c], 1);
}

__global__ void k_cellscan() {   // one block, 512 threads: exclusive scan + reset counts
  __shared__ int s[NCELL];
  int t = threadIdx.x;
  int x = g_ccnt[t];
  s[t] = x;
  __syncthreads();
  for (int o = 1; o < NCELL; o <<= 1) {
    int u = (t >= o) ? s[t-o] : 0;
    __syncthreads();
    s[t] += u;
    __syncthreads();
  }
  int start = s[t] - x;
  g_cstart[t] = start;
  g_cfill[t]  = start;
  g_ccnt[t]   = 0;                 // reset for graph replay determinism
  if (t == NCELL-1) g_cstart[NCELL] = s[t];
}

__global__ void k_scatter() {
  int i = blockIdx.x*blockDim.x + threadIdx.x;
  if (i >= NTOT) return;
  int c = g_cid[i];
  int pos = atomicAdd(&g_cfill[c], 1);
  g_sp[pos] = make_float4(g_xs[i], g_ys[i], g_zs[i], __int_as_float(i));
}

// ---------------- FPS v5: pruned cells, smem d[], atomic keys, 3 barriers/step ----------------
__global__ void __launch_bounds__(1024, 1) k_fps5() {
  extern __shared__ float sd[];                   // NTOT floats: running min sq-dist (80KB)
  __shared__ unsigned long long s_key[NCELL];     // (vbits<<24)|((0x7fff-orig)<<9)|cell
  __shared__ float s_thr[NCELL];                  // prune threshold on dc2
  __shared__ float s_mx[NCELL], s_my[NCELL], s_mz[NCELL];
  __shared__ int   s_start[NCELL+1];
  __shared__ short s_active[NCELL];
  __shared__ int   s_nact;
  __shared__ unsigned long long s_gk[2];          // double-buffered global max key

  int t = threadIdx.x;
  int lane = t & 31, w = t >> 5;

  for (int i = t; i < NTOT; i += 1024) sd[i] = 1e10f;
  if (t <= NCELL) s_start[t] = g_cstart[t];
  if (t < 2) s_gk[t] = 0ull;
  if (t == 0) s_nact = 0;
  __syncthreads();
  if (t < NCELL) {
    int cnt = s_start[t+1] - s_start[t];
    s_thr[t] = (cnt > 0) ? 4e10f : -1.0f;   // nonempty: active at step 1; empty: never
    s_key[t] = 0ull;
    s_mx[t]=0.f; s_my[t]=0.f; s_mz[t]=0.f;
  }
  float lx = g_ax[0], ly = g_ay[0], lz = g_az[0];  // center 0 (broadcast LDG)
  __syncthreads();

  for (int step = 1; step < NA; step++) {
    // Phase A: prune test + ballot compaction; zero keys of activated cells
    if (t < NCELL) {
      int ix = t & 7, iy = (t >> 3) & 7, iz = t >> 6;
      float dc2 = sqdist((ix+0.5f)*0.125f, (iy+0.5f)*0.125f, (iz+0.5f)*0.125f,
                         lx, ly, lz);
      bool act = dc2 <= s_thr[t];
      unsigned m = __ballot_sync(0xffffffffu, act);
      int base = 0;
      if (lane == 0 && m) base = atomicAdd(&s_nact, __popc(m));
      base = __shfl_sync(0xffffffffu, base, 0);
      if (act) {
        s_key[t] = 0ull;                            // rebuilt fresh in B
        s_active[base + __popc(m & ((1u << lane) - 1u))] = (short)t;
      }
    }
    __syncthreads();                                 // bar1
    int nact = s_nact;

    // Phase B: update active cells; per-lane atomicMax builds s_key[cell]
    for (int j = w; j < nact; j += 32) {
      int cell = (int)s_active[j];
      int st = s_start[cell], en = s_start[cell+1];
      unsigned long long myk = 0ull;
      float mx = 0.f, my = 0.f, mz = 0.f, mv = 0.f;
      for (int p0 = st; p0 < en; p0 += 32) {
        int p = p0 + lane;
        if (p < en) {
          float4 q = __ldg(&g_sp[p]);
          float dd = sqdist(q.x, q.y, q.z, lx, ly, lz);
          float nd = fminf(sd[p], dd);
          sd[p] = nd;
          unsigned orig = (unsigned)__float_as_int(q.w);
          unsigned long long k =
              ((unsigned long long)__float_as_uint(nd) << 24)
            | ((unsigned long long)(0x7fffu - orig) << 9)
            | (unsigned)cell;
          atomicMax(&s_key[cell], k);
          if (k > myk) { myk = k; mv = nd; mx = q.x; my = q.y; mz = q.z; }
        }
      }
      __syncwarp();
      if (myk != 0ull && myk == s_key[cell]) {       // unique winner lane
        s_mx[cell] = mx; s_my[cell] = my; s_mz[cell] = mz;
        float r = CELL_R + __fsqrt_rn(mv);
        s_thr[cell] = __fmul_rn(r, r) * 1.0002f;
      }
    }
    __syncthreads();                                 // bar2

    // Phase C: global max of 512 keys -> s_gk[step&1]; idle warp resets state
    if (t < NCELL) {
      unsigned long long k = s_key[t];
#pragma unroll
      for (int o = 16; o; o >>= 1) {
        unsigned long long ok = __shfl_xor_sync(0xffffffffu, k, o);
        if (ok > k) k = ok;
      }
      if (lane == 0) atomicMax(&s_gk[step & 1], k);
    } else if (t == 512) {
      s_nact = 0;
      s_gk[(step + 1) & 1] = 0ull;                   // slot last read before bar1
    }
    __syncthreads();                                 // bar3

    unsigned long long gk = s_gk[step & 1];
    int cell = (int)(gk & 511ull);
    lx = s_mx[cell]; ly = s_my[cell]; lz = s_mz[cell];
    if (t == 0) { g_ax[step] = lx; g_ay[step] = ly; g_az[step] = lz; }
  }
}

// ---------------- merged weight transposes ----------------
__global__ void k_transW(const float* __restrict__ sa_W1, const float* __restrict__ sa_W2,
                         const float* __restrict__ sa_W3, const float* __restrict__ fp_W1,
                         const float* __restrict__ fp_W2) {
  int i = blockIdx.x*blockDim.x + threadIdx.x;
  if (i < 163*128) { int k=i>>7, n=i&127; g_W1T[i] = sa_W1[n*163+k]; return; }
  i -= 163*128;
  if (i < 128*128) { int k=i>>7, n=i&127; g_W2T[i] = sa_W2[n*128+k]; return; }
  i -= 128*128;
  if (i < 128*128) { int k=i>>7, n=i&127; g_W3T[i] = sa_W3[n*128+k]; return; }
  i -= 128*128;
  if (i < 160*128) { int k=i>>7, n=i&127; g_fpW1T[i] = fp_W1[n*288+k]; return; } // cols>=160 hit zeros
  i -= 160*128;
  if (i < 128*32)  { int k=i>>5, n=i&31;  g_fpW2T[i] = fp_W2[n*128+k]; return; }
}

// ---------------- rgb feature transpose, smem-tiled ----------------
__global__ void k_transRGB(const float* __restrict__ W) { // W: [128, 15000]
  __shared__ float tile[32][33];
  int kb = blockIdx.x * 32;
  int nb = blockIdx.y * 32;
  int tx = threadIdx.x, ty = threadIdx.y;   // 32 x 8
#pragma unroll
  for (int j = 0; j < 4; j++) {
    int n = nb + ty + j*8, k = kb + tx;
    tile[ty + j*8][tx] = (k < N_RGB) ? W[(size_t)n*N_RGB + k] : 0.f;
  }
  __syncthreads();
#pragma unroll
  for (int j = 0; j < 4; j++) {
    int k = kb + ty + j*8, n = nb + tx;
    if (k < N_RGB) g_rgbT[(size_t)k*128 + n] = tile[tx][ty + j*8];
  }
}

// ---------------- ball query: first-k in-radius by INDEX, pad with first ----------------
__global__ void k_ballq(int mode) {
  int w    = (blockIdx.x*blockDim.x + threadIdx.x) >> 5;
  int lane = threadIdx.x & 31;
  int npoints, ks; float r2, cx, cy, cz; int* row;
  if (mode == 0) {
    if (w >= NA) return;
    npoints = NTOT; ks = SA_NS; r2 = 0.01f;       // f32(0.1*0.1)
    cx = g_ax[w]; cy = g_ay[w]; cz = g_az[w];
    row = g_nb + (size_t)w*SA_NS;
  } else {
    if (w >= N_PCD) return;
    npoints = N_PCD; ks = NB_K; r2 = 0.04f;       // f32(0.2*0.2)
    cx = g_xs[w]; cy = g_ys[w]; cz = g_zs[w];
    row = g_nb2 + (size_t)w*NB_K;
  }
  int cnt = 0;
  for (int bs = 0; bs < npoints && cnt < ks; bs += 32) {
    int i = bs + lane;
    bool in = false;
    if (i < npoints) {
      float dd = sqdist(g_xs[i], g_ys[i], g_zs[i], cx, cy, cz);
      in = dd < r2;
    }
    unsigned m = __ballot_sync(0xffffffffu, in);
    if (m) {
      int rnk = __popc(m & ((1u << lane) - 1u));
      int pos = cnt + rnk;
      if (in && pos < ks) row[pos] = i;
      cnt += __popc(m);
    }
  }
  __syncwarp();
  if (cnt < ks) {               // center always in-radius -> cnt >= 1
    int first = row[0];
    for (int j = cnt + lane; j < ks; j += 32) row[j] = first;
  }
}

// ---------------- gather G = [gxyz | pcd_feat | rgb_feat] ----------------
__global__ void k_gather(const float* __restrict__ pcd_feat) {
  int r = blockIdx.x;
  int t = threadIdx.x;
  if (t >= K1) return;
  int a = r >> 5;
  int p = g_nb[r];
  float v;
  if (t < 3) {
    float pc = (t == 0) ? g_xs[p] : (t == 1) ? g_ys[p] : g_zs[p];
    float ac = (t == 0) ? g_ax[a] : (t == 1) ? g_ay[a] : g_az[a];
    v = __fadd_rn(pc, -ac) / 0.1f;
  } else if (t < 35) {
    v = (p < N_PCD) ? pcd_feat[p*32 + (t-3)] : 0.f;
  } else {
    v = (p >= N_PCD) ? g_rgbT[(size_t)(p - N_PCD)*128 + (t-35)] : 0.f;
  }
  g_G[(size_t)r*K1 + t] = v;
}

// ---------------- SGEMM + bias + relu: M=131072, N=128 ----------------
__global__ void __launch_bounds__(256, 2)
k_gemm(int layer, const float* __restrict__ b1,
       const float* __restrict__ b2, const float* __restrict__ b3) {
  const float* A; const float* Bt; const float* bias; float* C; int K;
  if (layer == 0)      { A=g_G;  Bt=g_W1T; bias=b1; C=g_H1; K=K1;  }
  else if (layer == 1) { A=g_H1; Bt=g_W2T; bias=b2; C=g_H2; K=128; }
  else                 { A=g_H2; Bt=g_W3T; bias=b3; C=g_H1; K=128; }

  __shared__ float As[8*132];
  __shared__ float Bs[8*128];
  int t  = threadIdx.x;
  int m0 = blockIdx.x * 128;
  int ty = t >> 4, tx = t & 15;
  float acc[8][8];
#pragma unroll
  for (int r = 0; r < 8; r++)
#pragma unroll
    for (int c = 0; c < 8; c++) acc[r][c] = 0.f;

  for (int k0 = 0; k0 < K; k0 += 8) {
#pragma unroll
    for (int i = 0; i < 4; i++) {
      int idx = t + i*256;
      int ml = idx >> 3, kk = idx & 7;
      int kg = k0 + kk;
      As[kk*132 + ml] = (kg < K) ? A[(size_t)(m0+ml)*K + kg] : 0.f;
    }
#pragma unroll
    for (int i = 0; i < 4; i++) {
      int idx = t + i*256;
      int kk = idx >> 7, n = idx & 127;
      int kg = k0 + kk;
      Bs[kk*128 + n] = (kg < K) ? Bt[(size_t)kg*128 + n] : 0.f;
    }
    __syncthreads();
#pragma unroll
    for (int kk = 0; kk < 8; kk++) {
      float4 a0 = *(const float4*)&As[kk*132 + ty*8];
      float4 a1 = *(const float4*)&As[kk*132 + ty*8 + 4];
      float4 b0 = *(const float4*)&Bs[kk*128 + tx*8];
      float4 b1 = *(const float4*)&Bs[kk*128 + tx*8 + 4];
      float a[8] = {a0.x,a0.y,a0.z,a0.w,a1.x,a1.y,a1.z,a1.w};
      float b[8] = {b0.x,b0.y,b0.z,b0.w,b1.x,b1.y,b1.z,b1.w};
#pragma unroll
      for (int r = 0; r < 8; r++)
#pragma unroll
        for (int c = 0; c < 8; c++) acc[r][c] = fmaf(a[r], b[c], acc[r][c]);
    }
    __syncthreads();
  }
#pragma unroll
  for (int r = 0; r < 8; r++) {
    int m = m0 + ty*8 + r;
#pragma unroll
    for (int c = 0; c < 8; c++) {
      int n = tx*8 + c;
      float v = acc[r][c] + bias[n];
      C[(size_t)m*128 + n] = v > 0.f ? v : 0.f;
    }
  }
}

__global__ void k_maxpool() {
  int a = blockIdx.x, c = threadIdx.x;
  const float* base = g_H1 + (size_t)a*SA_NS*128 + c;
  float m = base[0];
#pragma unroll 4
  for (int s = 1; s < SA_NS; s++) m = fmaxf(m, base[(size_t)s*128]);
  g_saf[a*128 + c] = m;
}

// ---------------- 3-NN among anchors + inverse-distance weights ----------------
__global__ void k_nn3() {
  int i = blockIdx.x*blockDim.x + threadIdx.x;
  if (i >= N_PCD) return;
  float px = g_xs[i], py = g_ys[i], pz = g_zs[i];
  float d0 = 1e30f, d1 = 1e30f, d2 = 1e30f;
  int   i0 = 0, i1 = 0, i2 = 0;
  for (int a = 0; a < NA; a++) {
    float dd = sqdist(px, py, pz, g_ax[a], g_ay[a], g_az[a]);
    if (dd < d2) {                 // strict: earlier index wins ties (lax.top_k stable)
      if (dd < d1) {
        d2 = d1; i2 = i1;
        if (dd < d0) { d1 = d0; i1 = i0; d0 = dd; i0 = a; }
        else         { d1 = dd; i1 = a; }
      } else { d2 = dd; i2 = a; }
    }
  }
  float w0 = 1.0f/(d0 + 1e-8f), w1 = 1.0f/(d1 + 1e-8f), w2 = 1.0f/(d2 + 1e-8f);
  float ws = (w0 + w1) + w2;
  g_nn[i*3+0]=i0; g_nn[i*3+1]=i1; g_nn[i*3+2]=i2;
  g_wg[i*3+0]=w0/ws; g_wg[i*3+1]=w1/ws; g_wg[i*3+2]=w2/ws;
}

// ---------------- fused FP MLP (5000 pcd rows; effective K=160) ----------------
__global__ void k_fp(const float* __restrict__ pcd_feat,
                     const float* __restrict__ b1, const float* __restrict__ b2,
                     float* __restrict__ out_vf) {
  __shared__ float s_in[128];
  __shared__ float s_pf[32];
  __shared__ float s_h[128];
  int n = blockIdx.x, t = threadIdx.x;
  int i0 = g_nn[n*3+0], i1 = g_nn[n*3+1], i2 = g_nn[n*3+2];
  float w0 = g_wg[n*3+0], w1 = g_wg[n*3+1], w2 = g_wg[n*3+2];
  s_in[t] = w0*g_saf[i0*128+t] + w1*g_saf[i1*128+t] + w2*g_saf[i2*128+t];
  if (t < 32) s_pf[t] = pcd_feat[n*32 + t];
  __syncthreads();
  float acc = b1[t];
#pragma unroll 8
  for (int k = 0; k < 128; k++) acc = fmaf(s_in[k], g_fpW1T[k*128 + t], acc);
#pragma unroll 8
  for (int k = 0; k < 32; k++)  acc = fmaf(s_pf[k], g_fpW1T[(128+k)*128 + t], acc);
  s_h[t] = acc > 0.f ? acc : 0.f;
  __syncthreads();
  if (t < 32) {
    float a2 = b2[t];
#pragma unroll 8
    for (int k = 0; k < 128; k++) a2 = fmaf(s_h[k], g_fpW2T[k*32 + t], a2);
    float v = a2 > 0.f ? a2 : 0.f;
    g_fpf[n*32 + t] = v;
    atomicMax(&g_gmax, __float_as_uint(v));     // relu>=0 -> uint order == float order
    float sq = v*v;
#pragma unroll
    for (int off = 16; off; off >>= 1) sq += __shfl_xor_sync(0xffffffffu, sq, off);
    float nrm = fmaxf(sqrtf(sq), 1e-12f);
    out_vf[n*32 + t] = v / nrm;
  }
}

// ---------------- detection scores ----------------
__global__ void k_det(float* __restrict__ out_scores) {
  int i = blockIdx.x, c = threadIdx.x;   // 32 threads = 32 channels
  const int* nb = g_nb2 + (size_t)i*NB_K;
  float sum = 0.f;
#pragma unroll 4
  for (int j = 0; j < NB_K; j++) sum += g_fpf[nb[j]*32 + c];
  float s = __uint_as_float(g_gmax) + 1e-6f;
  float fi = g_fpf[i*32 + c] / s;
  float mean = (sum * (1.0f/64.0f)) / s;
  float x = fi - mean;
  float lm = fmaxf(x, 0.f) + log1pf(expf(-fabsf(x)));   // softplus
  float dwmax = fi;
#pragma unroll
  for (int off = 16; off; off >>= 1) dwmax = fmaxf(dwmax, __shfl_xor_sync(0xffffffffu, dwmax, off));
  float sc = lm * (fi / (1e-6f + dwmax));
#pragma unroll
  for (int off = 16; off; off >>= 1) sc = fmaxf(sc, __shfl_xor_sync(0xffffffffu, sc, off));
  if (c == 0) out_scores[i] = sc;
}

__global__ void k_out(const float* __restrict__ pcd_xyz, float* __restrict__ out) {
  int i = blockIdx.x*blockDim.x + threadIdx.x;
  if (i < N_PCD*3) out[i] = pcd_xyz[i];
}

extern "C" void kernel_launch(void* const* d_in, const int* in_sizes, int n_in,
                              void* d_out, int out_size) {
  (void)in_sizes; (void)n_in; (void)out_size;
  const float* pcd_xyz   = (const float*)d_in[0];
  const float* pcd_feat  = (const float*)d_in[1];
  const float* rgb_xyz   = (const float*)d_in[2];
  const float* rgb_feats = (const float*)d_in[3];
  const float* sa_W1 = (const float*)d_in[4];
  const float* sa_b1 = (const float*)d_in[5];
  const float* sa_W2 = (const float*)d_in[6];
  const float* sa_b2 = (const float*)d_in[7];
  const float* sa_W3 = (const float*)d_in[8];
  const float* sa_b3 = (const float*)d_in[9];
  const float* fp_W1 = (const float*)d_in[10];
  const float* fp_b1 = (const float*)d_in[11];
  const float* fp_W2 = (const float*)d_in[12];
  const float* fp_b2 = (const float*)d_in[13];
  float* out = (float*)d_out;
  float* out_scores = out + N_PCD*3;          // 15000..20000
  float* out_vf     = out + N_PCD*3 + N_PCD;  // 20000..180000

  static int smem_set = 0;
  if (!smem_set) {
    cudaFuncSetAttribute(k_fps5, cudaFuncAttributeMaxDynamicSharedMemorySize,
                         NTOT*(int)sizeof(float));
    smem_set = 1;
  }

  k_build<<<(NTOT+255)/256, 256>>>(pcd_xyz, rgb_xyz);           // 0
  k_cellscan<<<1, NCELL>>>();                                    // 1
  k_scatter<<<(NTOT+255)/256, 256>>>();                          // 2
  k_fps5<<<1, 1024, NTOT*sizeof(float)>>>();                     // 3  (ncu profiles this slot)
  k_transW<<<(78208+255)/256, 256>>>(sa_W1, sa_W2, sa_W3, fp_W1, fp_W2);
  { dim3 g((N_RGB+31)/32, 4), b(32, 8); k_transRGB<<<g, b>>>(rgb_feats); }
  k_ballq<<<(NA*32+255)/256, 256>>>(0);
  k_gather<<<NROWS, 192>>>(pcd_feat);
  k_gemm<<<NROWS/128, 256>>>(0, sa_b1, sa_b2, sa_b3);
  k_gemm<<<NROWS/128, 256>>>(1, sa_b1, sa_b2, sa_b3);
  k_gemm<<<NROWS/128, 256>>>(2, sa_b1, sa_b2, sa_b3);
  k_maxpool<<<NA, 128>>>();
  k_nn3<<<(N_PCD+255)/256, 256>>>();
  k_fp<<<N_PCD, 128>>>(pcd_feat, fp_b1, fp_b2, out_vf);
  k_ballq<<<(N_PCD*32+255)/256, 256>>>(1);
  k_det<<<N_PCD, 32>>>(out_scores);
  k_out<<<(N_PCD*3+255)/256, 256>>>(pcd_xyz, out);
}

// round 14
// speedup vs baseline: 1.3774x; 1.3774x over previous
#include <cuda_runtime.h>
#include <math.h>

#define N_PCD 5000
#define N_RGB 15000
#define NTOT  20000
#define NA    4096
#define SA_NS 32
#define NB_K  64
#define K1    163
#define NROWS (NA*SA_NS)
#define NCELL 512
#define CELL_R 0.10830f   /* > sqrt(3)/16 = 0.108253: conservative half-diagonal */

// ---------------- static device scratch ----------------
__device__ float g_xs[NTOT], g_ys[NTOT], g_zs[NTOT];
__device__ float g_ax[NA], g_ay[NA], g_az[NA];
__device__ int   g_nb[NA*SA_NS];
__device__ float g_rgbT[(size_t)N_RGB*128];
__device__ float g_W1T[K1*128];
__device__ float g_W2T[128*128];
__device__ float g_W3T[128*128];
__device__ float g_fpW1T[160*128];
__device__ float g_fpW2T[128*32];
__device__ float g_G [(size_t)NROWS*K1];
__device__ float g_H1[(size_t)NROWS*128];
__device__ float g_H2[(size_t)NROWS*128];
__device__ float g_saf[NA*128];
__device__ int   g_nn[N_PCD*3];
__device__ float g_wg[N_PCD*3];
__device__ float g_fpf[N_PCD*32];
__device__ int   g_nb2[N_PCD*NB_K];
__device__ unsigned int g_gmax;
// FPS cell structures
__device__ float4 g_sp[NTOT];          // sorted (x,y,z,orig-as-float-bits)
__device__ int    g_cid[NTOT];
__device__ int    g_ccnt[NCELL];
__device__ int    g_cstart[NCELL+1];
__device__ int    g_cfill[NCELL];

// (dx*dx + dy*dy) + dz*dz, contraction forbidden (FMA could flip argmax/top-k ties)
__device__ __forceinline__ float sqdist(float ax, float ay, float az,
                                        float bx, float by, float bz) {
  float dx = __fadd_rn(ax, -bx);
  float dy = __fadd_rn(ay, -by);
  float dz = __fadd_rn(az, -bz);
  return __fadd_rn(__fadd_rn(__fmul_rn(dx,dx), __fmul_rn(dy,dy)), __fmul_rn(dz,dz));
}

__device__ __forceinline__ int cell_of(float x, float y, float z) {
  int ix = min(7, max(0, (int)(x * 8.0f)));
  int iy = min(7, max(0, (int)(y * 8.0f)));
  int iz = min(7, max(0, (int)(z * 8.0f)));
  return (iz*8 + iy)*8 + ix;
}

// ---------------- prep: SoA xyz + cell id + counts, seed FPS step 0 ----------------
__global__ void k_build(const float* __restrict__ pcd_xyz,
                        const float* __restrict__ rgb_xyz) {
  int i = blockIdx.x*blockDim.x + threadIdx.x;
  if (i == 0) {
    g_gmax = 0u;
    g_ax[0] = pcd_xyz[0]; g_ay[0] = pcd_xyz[1]; g_az[0] = pcd_xyz[2];
  }
  if (i >= NTOT) return;
  float x, y, z;
  if (i < N_PCD) { x=pcd_xyz[i*3]; y=pcd_xyz[i*3+1]; z=pcd_xyz[i*3+2]; }
  else           { int j=i-N_PCD; x=rgb_xyz[j*3]; y=rgb_xyz[j*3+1]; z=rgb_xyz[j*3+2]; }
  g_xs[i]=x; g_ys[i]=y; g_zs[i]=z;
  int c = cell_of(x, y, z);
  g_cid[i] = c;
  atomicAdd(&g_ccnt[c], 1);
}

__global__ void k_cellscan() {   // one block, 512 threads: exclusive scan + reset counts
  __shared__ int s[NCELL];
  int t = threadIdx.x;
  int x = g_ccnt[t];
  s[t] = x;
  __syncthreads();
  for (int o = 1; o < NCELL; o <<= 1) {
    int u = (t >= o) ? s[t-o] : 0;
    __syncthreads();
    s[t] += u;
    __syncthreads();
  }
  int start = s[t] - x;
  g_cstart[t] = start;
  g_cfill[t]  = start;
  g_ccnt[t]   = 0;                 // reset for graph replay determinism
  if (t == NCELL-1) g_cstart[NCELL] = s[t];
}

__global__ void k_scatter() {
  int i = blockIdx.x*blockDim.x + threadIdx.x;
  if (i >= NTOT) return;
  int c = g_cid[i];
  int pos = atomicAdd(&g_cfill[c], 1);
  g_sp[pos] = make_float4(g_xs[i], g_ys[i], g_zs[i], __int_as_float(i));
}

// ---------------- FPS v6: pruned cells, smem d[], REDUX reductions, 3 barriers ----------------
__global__ void __launch_bounds__(1024, 1) k_fps6() {
  extern __shared__ float sd[];               // NTOT floats: running min sq-dist (80KB)
  __shared__ unsigned s_kd[NCELL];            // per-cell max d bits (float>=0 -> uint order)
  __shared__ unsigned s_kc[NCELL];            // per-cell (orig<<9)|cell for that max
  __shared__ float s_thr[NCELL];              // prune threshold on dc2
  __shared__ float s_mx[NCELL], s_my[NCELL], s_mz[NCELL];
  __shared__ int   s_start[NCELL+1];
  __shared__ short s_active[NCELL];
  __shared__ int   s_nact;
  __shared__ float s_center[4];

  int t = threadIdx.x;
  int lane = t & 31, w = t >> 5;

  for (int i = t; i < NTOT; i += 1024) sd[i] = 1e10f;
  if (t <= NCELL) s_start[t] = g_cstart[t];
  if (t == 0) s_nact = 0;
  __syncthreads();
  if (t < NCELL) {
    int cnt = s_start[t+1] - s_start[t];
    s_thr[t] = (cnt > 0) ? 4e10f : -1.0f;   // nonempty: active at step 1; empty: never
    s_kd[t] = 0u;
    s_kc[t] = 0xffffffffu;
    s_mx[t]=0.f; s_my[t]=0.f; s_mz[t]=0.f;
  }
  float lx = g_ax[0], ly = g_ay[0], lz = g_az[0];  // center 0 (broadcast LDG)
  __syncthreads();

  for (int step = 1; step < NA; step++) {
    // Phase A: prune test + ballot compaction (warps 0..15)
    if (t < NCELL) {
      int ix = t & 7, iy = (t >> 3) & 7, iz = t >> 6;
      float dc2 = sqdist((ix+0.5f)*0.125f, (iy+0.5f)*0.125f, (iz+0.5f)*0.125f,
                         lx, ly, lz);
      bool act = dc2 <= s_thr[t];
      unsigned m = __ballot_sync(0xffffffffu, act);
      int base = 0;
      if (lane == 0 && m) base = atomicAdd(&s_nact, __popc(m));
      base = __shfl_sync(0xffffffffu, base, 0);
      if (act) s_active[base + __popc(m & ((1u << lane) - 1u))] = (short)t;
    }
    __syncthreads();                                 // bar1
    int nact = s_nact;

    // Phase B: rescan active cells; 2x REDUX replaces the u64 shuffle tree
    for (int j = w; j < nact; j += 32) {
      int cell = (int)s_active[j];
      int st = s_start[cell], en = s_start[cell+1];
      unsigned bd = 0u, bc = 0xffffffffu;           // lane-best (d_bits, cand)
      float mx = 0.f, my = 0.f, mz = 0.f;
      for (int p0 = st; p0 < en; p0 += 32) {
        int p = p0 + lane;
        if (p < en) {
          float4 q = __ldg(&g_sp[p]);
          float dd = sqdist(q.x, q.y, q.z, lx, ly, lz);
          float nd = fminf(sd[p], dd);
          sd[p] = nd;
          unsigned db = __float_as_uint(nd);        // nd>=0: uint order == float order
          unsigned orig = (unsigned)__float_as_int(q.w);
          unsigned cd = (orig << 9) | (unsigned)cell;
          if (db > bd || (db == bd && cd < bc)) { bd = db; bc = cd; mx=q.x; my=q.y; mz=q.z; }
        }
      }
      unsigned wd = __reduce_max_sync(0xffffffffu, bd);
      unsigned cand = (bd == wd) ? bc : 0xffffffffu;
      unsigned wc = __reduce_min_sync(0xffffffffu, cand);
      if (bd == wd && bc == wc) {                   // unique winner lane (orig unique)
        s_kd[cell] = wd; s_kc[cell] = wc;
        s_mx[cell] = mx; s_my[cell] = my; s_mz[cell] = mz;
        float r = CELL_R + __fsqrt_rn(__uint_as_float(wd));
        s_thr[cell] = __fmul_rn(r, r) * 1.0002f;
      }
    }
    __syncthreads();                                 // bar2

    // Phase C: warp 0 reduces all 512 cells (conflict-free lane+32*i layout)
    if (w == 0) {
      unsigned bd = 0u, bc = 0xffffffffu;
#pragma unroll
      for (int i = 0; i < 16; i++) {
        int c = lane + (i << 5);
        unsigned d = s_kd[c], cd = s_kc[c];
        if (d > bd || (d == bd && cd < bc)) { bd = d; bc = cd; }
      }
      unsigned wd = __reduce_max_sync(0xffffffffu, bd);
      unsigned cand = (bd == wd) ? bc : 0xffffffffu;
      unsigned wc = __reduce_min_sync(0xffffffffu, cand);
      if (lane == 0) {
        int cell = (int)(wc & 511u);
        float bx = s_mx[cell], by = s_my[cell], bz = s_mz[cell];
        s_center[0] = bx; s_center[1] = by; s_center[2] = bz;
        g_ax[step] = bx; g_ay[step] = by; g_az[step] = bz;
        s_nact = 0;
      }
    }
    __syncthreads();                                 // bar3
    lx = s_center[0]; ly = s_center[1]; lz = s_center[2];
  }
}

// ---------------- merged weight transposes ----------------
__global__ void k_transW(const float* __restrict__ sa_W1, const float* __restrict__ sa_W2,
                         const float* __restrict__ sa_W3, const float* __restrict__ fp_W1,
                         const float* __restrict__ fp_W2) {
  int i = blockIdx.x*blockDim.x + threadIdx.x;
  if (i < 163*128) { int k=i>>7, n=i&127; g_W1T[i] = sa_W1[n*163+k]; return; }
  i -= 163*128;
  if (i < 128*128) { int k=i>>7, n=i&127; g_W2T[i] = sa_W2[n*128+k]; return; }
  i -= 128*128;
  if (i < 128*128) { int k=i>>7, n=i&127; g_W3T[i] = sa_W3[n*128+k]; return; }
  i -= 128*128;
  if (i < 160*128) { int k=i>>7, n=i&127; g_fpW1T[i] = fp_W1[n*288+k]; return; } // cols>=160 hit zeros
  i -= 160*128;
  if (i < 128*32)  { int k=i>>5, n=i&31;  g_fpW2T[i] = fp_W2[n*128+k]; return; }
}

// ---------------- rgb feature transpose, smem-tiled ----------------
__global__ void k_transRGB(const float* __restrict__ W) { // W: [128, 15000]
  __shared__ float tile[32][33];
  int kb = blockIdx.x * 32;
  int nb = blockIdx.y * 32;
  int tx = threadIdx.x, ty = threadIdx.y;   // 32 x 8
#pragma unroll
  for (int j = 0; j < 4; j++) {
    int n = nb + ty + j*8, k = kb + tx;
    tile[ty + j*8][tx] = (k < N_RGB) ? W[(size_t)n*N_RGB + k] : 0.f;
  }
  __syncthreads();
#pragma unroll
  for (int j = 0; j < 4; j++) {
    int k = kb + ty + j*8, n = nb + tx;
    if (k < N_RGB) g_rgbT[(size_t)k*128 + n] = tile[tx][ty + j*8];
  }
}

// ---------------- ball query: first-k in-radius by INDEX, pad with first ----------------
__global__ void k_ballq(int mode) {
  int w    = (blockIdx.x*blockDim.x + threadIdx.x) >> 5;
  int lane = threadIdx.x & 31;
  int npoints, ks; float r2, cx, cy, cz; int* row;
  if (mode == 0) {
    if (w >= NA) return;
    npoints = NTOT; ks = SA_NS; r2 = 0.01f;       // f32(0.1*0.1)
    cx = g_ax[w]; cy = g_ay[w]; cz = g_az[w];
    row = g_nb + (size_t)w*SA_NS;
  } else {
    if (w >= N_PCD) return;
    npoints = N_PCD; ks = NB_K; r2 = 0.04f;       // f32(0.2*0.2)
    cx = g_xs[w]; cy = g_ys[w]; cz = g_zs[w];
    row = g_nb2 + (size_t)w*NB_K;
  }
  int cnt = 0;
  for (int bs = 0; bs < npoints && cnt < ks; bs += 32) {
    int i = bs + lane;
    bool in = false;
    if (i < npoints) {
      float dd = sqdist(g_xs[i], g_ys[i], g_zs[i], cx, cy, cz);
      in = dd < r2;
    }
    unsigned m = __ballot_sync(0xffffffffu, in);
    if (m) {
      int rnk = __popc(m & ((1u << lane) - 1u));
      int pos = cnt + rnk;
      if (in && pos < ks) row[pos] = i;
      cnt += __popc(m);
    }
  }
  __syncwarp();
  if (cnt < ks) {               // center always in-radius -> cnt >= 1
    int first = row[0];
    for (int j = cnt + lane; j < ks; j += 32) row[j] = first;
  }
}

// ---------------- gather G = [gxyz | pcd_feat | rgb_feat] ----------------
__global__ void k_gather(const float* __restrict__ pcd_feat) {
  int r = blockIdx.x;
  int t = threadIdx.x;
  if (t >= K1) return;
  int a = r >> 5;
  int p = g_nb[r];
  float v;
  if (t < 3) {
    float pc = (t == 0) ? g_xs[p] : (t == 1) ? g_ys[p] : g_zs[p];
    float ac = (t == 0) ? g_ax[a] : (t == 1) ? g_ay[a] : g_az[a];
    v = __fadd_rn(pc, -ac) / 0.1f;
  } else if (t < 35) {
    v = (p < N_PCD) ? pcd_feat[p*32 + (t-3)] : 0.f;
  } else {
    v = (p >= N_PCD) ? g_rgbT[(size_t)(p - N_PCD)*128 + (t-35)] : 0.f;
  }
  g_G[(size_t)r*K1 + t] = v;
}

// ---------------- SGEMM + bias + relu: M=131072, N=128 ----------------
__global__ void __launch_bounds__(256, 2)
k_gemm(int layer, const float* __restrict__ b1,
       const float* __restrict__ b2, const float* __restrict__ b3) {
  const float* A; const float* Bt; const float* bias; float* C; int K;
  if (layer == 0)      { A=g_G;  Bt=g_W1T; bias=b1; C=g_H1; K=K1;  }
  else if (layer == 1) { A=g_H1; Bt=g_W2T; bias=b2; C=g_H2; K=128; }
  else                 { A=g_H2; Bt=g_W3T; bias=b3; C=g_H1; K=128; }

  __shared__ float As[8*132];
  __shared__ float Bs[8*128];
  int t  = threadIdx.x;
  int m0 = blockIdx.x * 128;
  int ty = t >> 4, tx = t & 15;
  float acc[8][8];
#pragma unroll
  for (int r = 0; r < 8; r++)
#pragma unroll
    for (int c = 0; c < 8; c++) acc[r][c] = 0.f;

  for (int k0 = 0; k0 < K; k0 += 8) {
#pragma unroll
    for (int i = 0; i < 4; i++) {
      int idx = t + i*256;
      int ml = idx >> 3, kk = idx & 7;
      int kg = k0 + kk;
      As[kk*132 + ml] = (kg < K) ? A[(size_t)(m0+ml)*K + kg] : 0.f;
    }
#pragma unroll
    for (int i = 0; i < 4; i++) {
      int idx = t + i*256;
      int kk = idx >> 7, n = idx & 127;
      int kg = k0 + kk;
      Bs[kk*128 + n] = (kg < K) ? Bt[(size_t)kg*128 + n] : 0.f;
    }
    __syncthreads();
#pragma unroll
    for (int kk = 0; kk < 8; kk++) {
      float4 a0 = *(const float4*)&As[kk*132 + ty*8];
      float4 a1 = *(const float4*)&As[kk*132 + ty*8 + 4];
      float4 b0 = *(const float4*)&Bs[kk*128 + tx*8];
      float4 b1 = *(const float4*)&Bs[kk*128 + tx*8 + 4];
      float a[8] = {a0.x,a0.y,a0.z,a0.w,a1.x,a1.y,a1.z,a1.w};
      float b[8] = {b0.x,b0.y,b0.z,b0.w,b1.x,b1.y,b1.z,b1.w};
#pragma unroll
      for (int r = 0; r < 8; r++)
#pragma unroll
        for (int c = 0; c < 8; c++) acc[r][c] = fmaf(a[r], b[c], acc[r][c]);
    }
    __syncthreads();
  }
#pragma unroll
  for (int r = 0; r < 8; r++) {
    int m = m0 + ty*8 + r;
#pragma unroll
    for (int c = 0; c < 8; c++) {
      int n = tx*8 + c;
      float v = acc[r][c] + bias[n];
      C[(size_t)m*128 + n] = v > 0.f ? v : 0.f;
    }
  }
}

__global__ void k_maxpool() {
  int a = blockIdx.x, c = threadIdx.x;
  const float* base = g_H1 + (size_t)a*SA_NS*128 + c;
  float m = base[0];
#pragma unroll 4
  for (int s = 1; s < SA_NS; s++) m = fmaxf(m, base[(size_t)s*128]);
  g_saf[a*128 + c] = m;
}

// ---------------- 3-NN among anchors + inverse-distance weights ----------------
__global__ void k_nn3() {
  int i = blockIdx.x*blockDim.x + threadIdx.x;
  if (i >= N_PCD) return;
  float px = g_xs[i], py = g_ys[i], pz = g_zs[i];
  float d0 = 1e30f, d1 = 1e30f, d2 = 1e30f;
  int   i0 = 0, i1 = 0, i2 = 0;
  for (int a = 0; a < NA; a++) {
    float dd = sqdist(px, py, pz, g_ax[a], g_ay[a], g_az[a]);
    if (dd < d2) {                 // strict: earlier index wins ties (lax.top_k stable)
      if (dd < d1) {
        d2 = d1; i2 = i1;
        if (dd < d0) { d1 = d0; i1 = i0; d0 = dd; i0 = a; }
        else         { d1 = dd; i1 = a; }
      } else { d2 = dd; i2 = a; }
    }
  }
  float w0 = 1.0f/(d0 + 1e-8f), w1 = 1.0f/(d1 + 1e-8f), w2 = 1.0f/(d2 + 1e-8f);
  float ws = (w0 + w1) + w2;
  g_nn[i*3+0]=i0; g_nn[i*3+1]=i1; g_nn[i*3+2]=i2;
  g_wg[i*3+0]=w0/ws; g_wg[i*3+1]=w1/ws; g_wg[i*3+2]=w2/ws;
}

// ---------------- fused FP MLP (5000 pcd rows; effective K=160) ----------------
__global__ void k_fp(const float* __restrict__ pcd_feat,
                     const float* __restrict__ b1, const float* __restrict__ b2,
                     float* __restrict__ out_vf) {
  __shared__ float s_in[128];
  __shared__ float s_pf[32];
  __shared__ float s_h[128];
  int n = blockIdx.x, t = threadIdx.x;
  int i0 = g_nn[n*3+0], i1 = g_nn[n*3+1], i2 = g_nn[n*3+2];
  float w0 = g_wg[n*3+0], w1 = g_wg[n*3+1], w2 = g_wg[n*3+2];
  s_in[t] = w0*g_saf[i0*128+t] + w1*g_saf[i1*128+t] + w2*g_saf[i2*128+t];
  if (t < 32) s_pf[t] = pcd_feat[n*32 + t];
  __syncthreads();
  float acc = b1[t];
#pragma unroll 8
  for (int k = 0; k < 128; k++) acc = fmaf(s_in[k], g_fpW1T[k*128 + t], acc);
#pragma unroll 8
  for (int k = 0; k < 32; k++)  acc = fmaf(s_pf[k], g_fpW1T[(128+k)*128 + t], acc);
  s_h[t] = acc > 0.f ? acc : 0.f;
  __syncthreads();
  if (t < 32) {
    float a2 = b2[t];
#pragma unroll 8
    for (int k = 0; k < 128; k++) a2 = fmaf(s_h[k], g_fpW2T[k*32 + t], a2);
    float v = a2 > 0.f ? a2 : 0.f;
    g_fpf[n*32 + t] = v;
    atomicMax(&g_gmax, __float_as_uint(v));     // relu>=0 -> uint order == float order
    float sq = v*v;
#pragma unroll
    for (int off = 16; off; off >>= 1) sq += __shfl_xor_sync(0xffffffffu, sq, off);
    float nrm = fmaxf(sqrtf(sq), 1e-12f);
    out_vf[n*32 + t] = v / nrm;
  }
}

// ---------------- detection scores ----------------
__global__ void k_det(float* __restrict__ out_scores) {
  int i = blockIdx.x, c = threadIdx.x;   // 32 threads = 32 channels
  const int* nb = g_nb2 + (size_t)i*NB_K;
  float sum = 0.f;
#pragma unroll 4
  for (int j = 0; j < NB_K; j++) sum += g_fpf[nb[j]*32 + c];
  float s = __uint_as_float(g_gmax) + 1e-6f;
  float fi = g_fpf[i*32 + c] / s;
  float mean = (sum * (1.0f/64.0f)) / s;
  float x = fi - mean;
  float lm = fmaxf(x, 0.f) + log1pf(expf(-fabsf(x)));   // softplus
  float dwmax = fi;
#pragma unroll
  for (int off = 16; off; off >>= 1) dwmax = fmaxf(dwmax, __shfl_xor_sync(0xffffffffu, dwmax, off));
  float sc = lm * (fi / (1e-6f + dwmax));
#pragma unroll
  for (int off = 16; off; off >>= 1) sc = fmaxf(sc, __shfl_xor_sync(0xffffffffu, sc, off));
  if (c == 0) out_scores[i] = sc;
}

__global__ void k_out(const float* __restrict__ pcd_xyz, float* __restrict__ out) {
  int i = blockIdx.x*blockDim.x + threadIdx.x;
  if (i < N_PCD*3) out[i] = pcd_xyz[i];
}

extern "C" void kernel_launch(void* const* d_in, const int* in_sizes, int n_in,
                              void* d_out, int out_size) {
  (void)in_sizes; (void)n_in; (void)out_size;
  const float* pcd_xyz   = (const float*)d_in[0];
  const float* pcd_feat  = (const float*)d_in[1];
  const float* rgb_xyz   = (const float*)d_in[2];
  const float* rgb_feats = (const float*)d_in[3];
  const float* sa_W1 = (const float*)d_in[4];
  const float* sa_b1 = (const float*)d_in[5];
  const float* sa_W2 = (const float*)d_in[6];
  const float* sa_b2 = (const float*)d_in[7];
  const float* sa_W3 = (const float*)d_in[8];
  const float* sa_b3 = (const float*)d_in[9];
  const float* fp_W1 = (const float*)d_in[10];
  const float* fp_b1 = (const float*)d_in[11];
  const float* fp_W2 = (const float*)d_in[12];
  const float* fp_b2 = (const float*)d_in[13];
  float* out = (float*)d_out;
  float* out_scores = out + N_PCD*3;          // 15000..20000
  float* out_vf     = out + N_PCD*3 + N_PCD;  // 20000..180000

  static int smem_set = 0;
  if (!smem_set) {
    cudaFuncSetAttribute(k_fps6, cudaFuncAttributeMaxDynamicSharedMemorySize,
                         NTOT*(int)sizeof(float));
    smem_set = 1;
  }

  k_build<<<(NTOT+255)/256, 256>>>(pcd_xyz, rgb_xyz);           // 0
  k_cellscan<<<1, NCELL>>>();                                    // 1
  k_scatter<<<(NTOT+255)/256, 256>>>();                          // 2
  k_fps6<<<1, 1024, NTOT*sizeof(float)>>>();                     // 3  (ncu profiles this slot)
  k_transW<<<(78208+255)/256, 256>>>(sa_W1, sa_W2, sa_W3, fp_W1, fp_W2);
  { dim3 g((N_RGB+31)/32, 4), b(32, 8); k_transRGB<<<g, b>>>(rgb_feats); }
  k_ballq<<<(NA*32+255)/256, 256>>>(0);
  k_gather<<<NROWS, 192>>>(pcd_feat);
  k_gemm<<<NROWS/128, 256>>>(0, sa_b1, sa_b2, sa_b3);
  k_gemm<<<NROWS/128, 256>>>(1, sa_b1, sa_b2, sa_b3);
  k_gemm<<<NROWS/128, 256>>>(2, sa_b1, sa_b2, sa_b3);
  k_maxpool<<<NA, 128>>>();
  k_nn3<<<(N_PCD+255)/256, 256>>>();
  k_fp<<<N_PCD, 128>>>(pcd_feat, fp_b1, fp_b2, out_vf);
  k_ballq<<<(N_PCD*32+255)/256, 256>>>(1);
  k_det<<<N_PCD, 32>>>(out_scores);
  k_out<<<(N_PCD*3+255)/256, 256>>>(pcd_xyz, out);
}

// round 15
// speedup vs baseline: 1.5098x; 1.0961x over previous
#include <cuda_runtime.h>
#include <math.h>

#define N_PCD 5000
#define N_RGB 15000
#define NTOT  20000
#define NA    4096
#define SA_NS 32
#define NB_K  64
#define K1    163
#define NROWS (NA*SA_NS)
#define NCELL 512

// ---------------- static device scratch ----------------
__device__ float g_xs[NTOT], g_ys[NTOT], g_zs[NTOT];
__device__ float g_ax[NA], g_ay[NA], g_az[NA];
__device__ int   g_nb[NA*SA_NS];
__device__ float g_rgbT[(size_t)N_RGB*128];
__device__ float g_W1T[K1*128];
__device__ float g_W2T[128*128];
__device__ float g_W3T[128*128];
__device__ float g_fpW1T[160*128];
__device__ float g_fpW2T[128*32];
__device__ float g_G [(size_t)NROWS*K1];
__device__ float g_H1[(size_t)NROWS*128];
__device__ float g_H2[(size_t)NROWS*128];
__device__ float g_saf[NA*128];
__device__ int   g_nn[N_PCD*3];
__device__ float g_wg[N_PCD*3];
__device__ float g_fpf[N_PCD*32];
__device__ int   g_nb2[N_PCD*NB_K];
__device__ unsigned int g_gmax;
// FPS cell structures
__device__ float4 g_sp[NTOT];          // sorted (x,y,z,orig-as-float-bits)
__device__ int    g_cid[NTOT];
__device__ int    g_ccnt[NCELL];
__device__ int    g_cstart[NCELL+1];
__device__ int    g_cfill[NCELL];

// (dx*dx + dy*dy) + dz*dz, contraction forbidden (FMA could flip argmax/top-k ties)
__device__ __forceinline__ float sqdist(float ax, float ay, float az,
                                        float bx, float by, float bz) {
  float dx = __fadd_rn(ax, -bx);
  float dy = __fadd_rn(ay, -by);
  float dz = __fadd_rn(az, -bz);
  return __fadd_rn(__fadd_rn(__fmul_rn(dx,dx), __fmul_rn(dy,dy)), __fmul_rn(dz,dz));
}

__device__ __forceinline__ int cell_of(float x, float y, float z) {
  int ix = min(7, max(0, (int)(x * 8.0f)));
  int iy = min(7, max(0, (int)(y * 8.0f)));
  int iz = min(7, max(0, (int)(z * 8.0f)));
  return (iz*8 + iy)*8 + ix;
}

// ---------------- prep: SoA xyz + cell id + counts, seed FPS step 0 ----------------
__global__ void k_build(const float* __restrict__ pcd_xyz,
                        const float* __restrict__ rgb_xyz) {
  int i = blockIdx.x*blockDim.x + threadIdx.x;
  if (i == 0) {
    g_gmax = 0u;
    g_ax[0] = pcd_xyz[0]; g_ay[0] = pcd_xyz[1]; g_az[0] = pcd_xyz[2];
  }
  if (i >= NTOT) return;
  float x, y, z;
  if (i < N_PCD) { x=pcd_xyz[i*3]; y=pcd_xyz[i*3+1]; z=pcd_xyz[i*3+2]; }
  else           { int j=i-N_PCD; x=rgb_xyz[j*3]; y=rgb_xyz[j*3+1]; z=rgb_xyz[j*3+2]; }
  g_xs[i]=x; g_ys[i]=y; g_zs[i]=z;
  int c = cell_of(x, y, z);
  g_cid[i] = c;
  atomicAdd(&g_ccnt[c], 1);
}

__global__ void k_cellscan() {   // one block, 512 threads: exclusive scan + reset counts
  __shared__ int s[NCELL];
  int t = threadIdx.x;
  int x = g_ccnt[t];
  s[t] = x;
  __syncthreads();
  for (int o = 1; o < NCELL; o <<= 1) {
    int u = (t >= o) ? s[t-o] : 0;
    __syncthreads();
    s[t] += u;
    __syncthreads();
  }
  int start = s[t] - x;
  g_cstart[t] = start;
  g_cfill[t]  = start;
  g_ccnt[t]   = 0;                 // reset for graph replay determinism
  if (t == NCELL-1) g_cstart[NCELL] = s[t];
}

__global__ void k_scatter() {
  int i = blockIdx.x*blockDim.x + threadIdx.x;
  if (i >= NTOT) return;
  int c = g_cid[i];
  int pos = atomicAdd(&g_cfill[c], 1);
  g_sp[pos] = make_float4(g_xs[i], g_ys[i], g_zs[i], __int_as_float(i));
}

// ---------------- FPS v7: exact-AABB prune, packed u64 keys, REDUX ----------------
// key = (d_bits<<32) | (0xffffffff - ((orig<<9)|cell)) : u64 max == max d, tie -> min orig
__global__ void __launch_bounds__(1024, 1) k_fps7() {
  extern __shared__ float sd[];                    // NTOT floats: running min sq-dist (80KB)
  __shared__ unsigned long long s_k64[NCELL];
  __shared__ float s_mx[NCELL], s_my[NCELL], s_mz[NCELL];
  __shared__ int   s_start[NCELL+1];
  __shared__ short s_active[NCELL];
  __shared__ int   s_nact;
  __shared__ float s_center[4];

  int t = threadIdx.x;
  int lane = t & 31, w = t >> 5;

  for (int i = t; i < NTOT; i += 1024) sd[i] = 1e10f;
  if (t <= NCELL) s_start[t] = g_cstart[t];
  if (t == 0) s_nact = 0;
  __syncthreads();
  // loop-invariant AABB bounds for this thread's cell
  float alo_x=0.f, ahi_x=0.f, alo_y=0.f, ahi_y=0.f, alo_z=0.f, ahi_z=0.f;
  if (t < NCELL) {
    int cnt = s_start[t+1] - s_start[t];
    s_k64[t] = cnt > 0 ? ((unsigned long long)__float_as_uint(4e10f) << 32) : 0ull;
    s_mx[t]=0.f; s_my[t]=0.f; s_mz[t]=0.f;
    int ix = t & 7, iy = (t >> 3) & 7, iz = t >> 6;
    alo_x = ix*0.125f; ahi_x = alo_x + 0.125f;
    alo_y = iy*0.125f; ahi_y = alo_y + 0.125f;
    alo_z = iz*0.125f; ahi_z = alo_z + 0.125f;
  }
  float lx = g_ax[0], ly = g_ay[0], lz = g_az[0];  // center 0 (broadcast LDG)
  __syncthreads();

  for (int step = 1; step < NA; step++) {
    // Phase A: exact AABB prune + ballot compaction (warps 0..15)
    if (t < NCELL) {
      float dx = fmaxf(fmaxf(alo_x - lx, lx - ahi_x), 0.f);
      float dy = fmaxf(fmaxf(alo_y - ly, ly - ahi_y), 0.f);
      float dz = fmaxf(fmaxf(alo_z - lz, lz - ahi_z), 0.f);
      float aabb2 = dx*dx + dy*dy + dz*dz;
      float dmax = __uint_as_float((unsigned)(s_k64[t] >> 32));
      bool act = aabb2 * 0.9999f <= dmax;          // skip only when provably no-op
      unsigned m = __ballot_sync(0xffffffffu, act);
      int base = 0;
      if (lane == 0 && m) base = atomicAdd(&s_nact, __popc(m));
      base = __shfl_sync(0xffffffffu, base, 0);
      if (act) s_active[base + __popc(m & ((1u << lane) - 1u))] = (short)t;
    }
    __syncthreads();                                 // bar1
    int nact = s_nact;

    // Phase B: rescan active cells; REDUX pair picks unique winner lane
    for (int j = w; j < nact; j += 32) {
      int cell = (int)s_active[j];
      int st = s_start[cell], en = s_start[cell+1];
      unsigned bd = 0u, bc = 0xffffffffu;           // lane-best (d_bits, (orig<<9)|cell)
      float mx = 0.f, my = 0.f, mz = 0.f;
      for (int p0 = st; p0 < en; p0 += 32) {
        int p = p0 + lane;
        if (p < en) {
          float4 q = __ldg(&g_sp[p]);
          float dd = sqdist(q.x, q.y, q.z, lx, ly, lz);
          float nd = fminf(sd[p], dd);
          sd[p] = nd;
          unsigned db = __float_as_uint(nd);        // nd>=0: uint order == float order
          unsigned orig = (unsigned)__float_as_int(q.w);
          unsigned cd = (orig << 9) | (unsigned)cell;
          if (db > bd || (db == bd && cd < bc)) { bd = db; bc = cd; mx=q.x; my=q.y; mz=q.z; }
        }
      }
      unsigned wd = __reduce_max_sync(0xffffffffu, bd);
      unsigned cand = (bd == wd) ? bc : 0xffffffffu;
      unsigned wc = __reduce_min_sync(0xffffffffu, cand);
      if (bd == wd && bc == wc) {                   // unique winner lane (orig unique)
        s_k64[cell] = ((unsigned long long)wd << 32) | (0xffffffffu - wc);
        s_mx[cell] = mx; s_my[cell] = my; s_mz[cell] = mz;
      }
    }
    if (t == 1023) s_nact = 0;                      // after all read nact, before bar2
    __syncthreads();                                 // bar2

    // Phase C: warp 0 reduces all 512 packed keys (conflict-free lane+32*i layout)
    if (w == 0) {
      unsigned long long bk = 0ull;
#pragma unroll
      for (int i = 0; i < 16; i++) {
        unsigned long long k = s_k64[lane + (i << 5)];
        if (k > bk) bk = k;
      }
      unsigned hi = (unsigned)(bk >> 32), lo = (unsigned)(bk & 0xffffffffu);
      unsigned whi = __reduce_max_sync(0xffffffffu, hi);
      unsigned cl = (hi == whi) ? lo : 0u;
      unsigned wlo = __reduce_max_sync(0xffffffffu, cl);   // max(~cd) == min cd
      if (lane == 0) {
        int cell = (int)((0xffffffffu - wlo) & 511u);
        float bx = s_mx[cell], by = s_my[cell], bz = s_mz[cell];
        s_center[0] = bx; s_center[1] = by; s_center[2] = bz;
        g_ax[step] = bx; g_ay[step] = by; g_az[step] = bz;
      }
    }
    __syncthreads();                                 // bar3
    lx = s_center[0]; ly = s_center[1]; lz = s_center[2];
  }
}

// ---------------- merged weight transposes ----------------
__global__ void k_transW(const float* __restrict__ sa_W1, const float* __restrict__ sa_W2,
                         const float* __restrict__ sa_W3, const float* __restrict__ fp_W1,
                         const float* __restrict__ fp_W2) {
  int i = blockIdx.x*blockDim.x + threadIdx.x;
  if (i < 163*128) { int k=i>>7, n=i&127; g_W1T[i] = sa_W1[n*163+k]; return; }
  i -= 163*128;
  if (i < 128*128) { int k=i>>7, n=i&127; g_W2T[i] = sa_W2[n*128+k]; return; }
  i -= 128*128;
  if (i < 128*128) { int k=i>>7, n=i&127; g_W3T[i] = sa_W3[n*128+k]; return; }
  i -= 128*128;
  if (i < 160*128) { int k=i>>7, n=i&127; g_fpW1T[i] = fp_W1[n*288+k]; return; } // cols>=160 hit zeros
  i -= 160*128;
  if (i < 128*32)  { int k=i>>5, n=i&31;  g_fpW2T[i] = fp_W2[n*128+k]; return; }
}

// ---------------- rgb feature transpose, smem-tiled ----------------
__global__ void k_transRGB(const float* __restrict__ W) { // W: [128, 15000]
  __shared__ float tile[32][33];
  int kb = blockIdx.x * 32;
  int nb = blockIdx.y * 32;
  int tx = threadIdx.x, ty = threadIdx.y;   // 32 x 8
#pragma unroll
  for (int j = 0; j < 4; j++) {
    int n = nb + ty + j*8, k = kb + tx;
    tile[ty + j*8][tx] = (k < N_RGB) ? W[(size_t)n*N_RGB + k] : 0.f;
  }
  __syncthreads();
#pragma unroll
  for (int j = 0; j < 4; j++) {
    int k = kb + ty + j*8, n = nb + tx;
    if (k < N_RGB) g_rgbT[(size_t)k*128 + n] = tile[tx][ty + j*8];
  }
}

// ---------------- ball query: first-k in-radius by INDEX, pad with first ----------------
__global__ void k_ballq(int mode) {
  int w    = (blockIdx.x*blockDim.x + threadIdx.x) >> 5;
  int lane = threadIdx.x & 31;
  int npoints, ks; float r2, cx, cy, cz; int* row;
  if (mode == 0) {
    if (w >= NA) return;
    npoints = NTOT; ks = SA_NS; r2 = 0.01f;       // f32(0.1*0.1)
    cx = g_ax[w]; cy = g_ay[w]; cz = g_az[w];
    row = g_nb + (size_t)w*SA_NS;
  } else {
    if (w >= N_PCD) return;
    npoints = N_PCD; ks = NB_K; r2 = 0.04f;       // f32(0.2*0.2)
    cx = g_xs[w]; cy = g_ys[w]; cz = g_zs[w];
    row = g_nb2 + (size_t)w*NB_K;
  }
  int cnt = 0;
  for (int bs = 0; bs < npoints && cnt < ks; bs += 32) {
    int i = bs + lane;
    bool in = false;
    if (i < npoints) {
      float dd = sqdist(g_xs[i], g_ys[i], g_zs[i], cx, cy, cz);
      in = dd < r2;
    }
    unsigned m = __ballot_sync(0xffffffffu, in);
    if (m) {
      int rnk = __popc(m & ((1u << lane) - 1u));
      int pos = cnt + rnk;
      if (in && pos < ks) row[pos] = i;
      cnt += __popc(m);
    }
  }
  __syncwarp();
  if (cnt < ks) {               // center always in-radius -> cnt >= 1
    int first = row[0];
    for (int j = cnt + lane; j < ks; j += 32) row[j] = first;
  }
}

// ---------------- gather G = [gxyz | pcd_feat | rgb_feat] ----------------
__global__ void k_gather(const float* __restrict__ pcd_feat) {
  int r = blockIdx.x;
  int t = threadIdx.x;
  if (t >= K1) return;
  int a = r >> 5;
  int p = g_nb[r];
  float v;
  if (t < 3) {
    float pc = (t == 0) ? g_xs[p] : (t == 1) ? g_ys[p] : g_zs[p];
    float ac = (t == 0) ? g_ax[a] : (t == 1) ? g_ay[a] : g_az[a];
    v = __fadd_rn(pc, -ac) / 0.1f;
  } else if (t < 35) {
    v = (p < N_PCD) ? pcd_feat[p*32 + (t-3)] : 0.f;
  } else {
    v = (p >= N_PCD) ? g_rgbT[(size_t)(p - N_PCD)*128 + (t-35)] : 0.f;
  }
  g_G[(size_t)r*K1 + t] = v;
}

// ---------------- SGEMM + bias + relu: M=131072, N=128 ----------------
__global__ void __launch_bounds__(256, 2)
k_gemm(int layer, const float* __restrict__ b1,
       const float* __restrict__ b2, const float* __restrict__ b3) {
  const float* A; const float* Bt; const float* bias; float* C; int K;
  if (layer == 0)      { A=g_G;  Bt=g_W1T; bias=b1; C=g_H1; K=K1;  }
  else if (layer == 1) { A=g_H1; Bt=g_W2T; bias=b2; C=g_H2; K=128; }
  else                 { A=g_H2; Bt=g_W3T; bias=b3; C=g_H1; K=128; }

  __shared__ float As[8*132];
  __shared__ float Bs[8*128];
  int t  = threadIdx.x;
  int m0 = blockIdx.x * 128;
  int ty = t >> 4, tx = t & 15;
  float acc[8][8];
#pragma unroll
  for (int r = 0; r < 8; r++)
#pragma unroll
    for (int c = 0; c < 8; c++) acc[r][c] = 0.f;

  for (int k0 = 0; k0 < K; k0 += 8) {
#pragma unroll
    for (int i = 0; i < 4; i++) {
      int idx = t + i*256;
      int ml = idx >> 3, kk = idx & 7;
      int kg = k0 + kk;
      As[kk*132 + ml] = (kg < K) ? A[(size_t)(m0+ml)*K + kg] : 0.f;
    }
#pragma unroll
    for (int i = 0; i < 4; i++) {
      int idx = t + i*256;
      int kk = idx >> 7, n = idx & 127;
      int kg = k0 + kk;
      Bs[kk*128 + n] = (kg < K) ? Bt[(size_t)kg*128 + n] : 0.f;
    }
    __syncthreads();
#pragma unroll
    for (int kk = 0; kk < 8; kk++) {
      float4 a0 = *(const float4*)&As[kk*132 + ty*8];
      float4 a1 = *(const float4*)&As[kk*132 + ty*8 + 4];
      float4 b0 = *(const float4*)&Bs[kk*128 + tx*8];
      float4 b1 = *(const float4*)&Bs[kk*128 + tx*8 + 4];
      float a[8] = {a0.x,a0.y,a0.z,a0.w,a1.x,a1.y,a1.z,a1.w};
      float b[8] = {b0.x,b0.y,b0.z,b0.w,b1.x,b1.y,b1.z,b1.w};
#pragma unroll
      for (int r = 0; r < 8; r++)
#pragma unroll
        for (int c = 0; c < 8; c++) acc[r][c] = fmaf(a[r], b[c], acc[r][c]);
    }
    __syncthreads();
  }
#pragma unroll
  for (int r = 0; r < 8; r++) {
    int m = m0 + ty*8 + r;
#pragma unroll
    for (int c = 0; c < 8; c++) {
      int n = tx*8 + c;
      float v = acc[r][c] + bias[n];
      C[(size_t)m*128 + n] = v > 0.f ? v : 0.f;
    }
  }
}

__global__ void k_maxpool() {
  int a = blockIdx.x, c = threadIdx.x;
  const float* base = g_H1 + (size_t)a*SA_NS*128 + c;
  float m = base[0];
#pragma unroll 4
  for (int s = 1; s < SA_NS; s++) m = fmaxf(m, base[(size_t)s*128]);
  g_saf[a*128 + c] = m;
}

// ---------------- 3-NN among anchors + inverse-distance weights ----------------
__global__ void k_nn3() {
  int i = blockIdx.x*blockDim.x + threadIdx.x;
  if (i >= N_PCD) return;
  float px = g_xs[i], py = g_ys[i], pz = g_zs[i];
  float d0 = 1e30f, d1 = 1e30f, d2 = 1e30f;
  int   i0 = 0, i1 = 0, i2 = 0;
  for (int a = 0; a < NA; a++) {
    float dd = sqdist(px, py, pz, g_ax[a], g_ay[a], g_az[a]);
    if (dd < d2) {                 // strict: earlier index wins ties (lax.top_k stable)
      if (dd < d1) {
        d2 = d1; i2 = i1;
        if (dd < d0) { d1 = d0; i1 = i0; d0 = dd; i0 = a; }
        else         { d1 = dd; i1 = a; }
      } else { d2 = dd; i2 = a; }
    }
  }
  float w0 = 1.0f/(d0 + 1e-8f), w1 = 1.0f/(d1 + 1e-8f), w2 = 1.0f/(d2 + 1e-8f);
  float ws = (w0 + w1) + w2;
  g_nn[i*3+0]=i0; g_nn[i*3+1]=i1; g_nn[i*3+2]=i2;
  g_wg[i*3+0]=w0/ws; g_wg[i*3+1]=w1/ws; g_wg[i*3+2]=w2/ws;
}

// ---------------- fused FP MLP (5000 pcd rows; effective K=160) ----------------
__global__ void k_fp(const float* __restrict__ pcd_feat,
                     const float* __restrict__ b1, const float* __restrict__ b2,
                     float* __restrict__ out_vf) {
  __shared__ float s_in[128];
  __shared__ float s_pf[32];
  __shared__ float s_h[128];
  int n = blockIdx.x, t = threadIdx.x;
  int i0 = g_nn[n*3+0], i1 = g_nn[n*3+1], i2 = g_nn[n*3+2];
  float w0 = g_wg[n*3+0], w1 = g_wg[n*3+1], w2 = g_wg[n*3+2];
  s_in[t] = w0*g_saf[i0*128+t] + w1*g_saf[i1*128+t] + w2*g_saf[i2*128+t];
  if (t < 32) s_pf[t] = pcd_feat[n*32 + t];
  __syncthreads();
  float acc = b1[t];
#pragma unroll 8
  for (int k = 0; k < 128; k++) acc = fmaf(s_in[k], g_fpW1T[k*128 + t], acc);
#pragma unroll 8
  for (int k = 0; k < 32; k++)  acc = fmaf(s_pf[k], g_fpW1T[(128+k)*128 + t], acc);
  s_h[t] = acc > 0.f ? acc : 0.f;
  __syncthreads();
  if (t < 32) {
    float a2 = b2[t];
#pragma unroll 8
    for (int k = 0; k < 128; k++) a2 = fmaf(s_h[k], g_fpW2T[k*32 + t], a2);
    float v = a2 > 0.f ? a2 : 0.f;
    g_fpf[n*32 + t] = v;
    atomicMax(&g_gmax, __float_as_uint(v));     // relu>=0 -> uint order == float order
    float sq = v*v;
#pragma unroll
    for (int off = 16; off; off >>= 1) sq += __shfl_xor_sync(0xffffffffu, sq, off);
    float nrm = fmaxf(sqrtf(sq), 1e-12f);
    out_vf[n*32 + t] = v / nrm;
  }
}

// ---------------- detection scores ----------------
__global__ void k_det(float* __restrict__ out_scores) {
  int i = blockIdx.x, c = threadIdx.x;   // 32 threads = 32 channels
  const int* nb = g_nb2 + (size_t)i*NB_K;
  float sum = 0.f;
#pragma unroll 4
  for (int j = 0; j < NB_K; j++) sum += g_fpf[nb[j]*32 + c];
  float s = __uint_as_float(g_gmax) + 1e-6f;
  float fi = g_fpf[i*32 + c] / s;
  float mean = (sum * (1.0f/64.0f)) / s;
  float x = fi - mean;
  float lm = fmaxf(x, 0.f) + log1pf(expf(-fabsf(x)));   // softplus
  float dwmax = fi;
#pragma unroll
  for (int off = 16; off; off >>= 1) dwmax = fmaxf(dwmax, __shfl_xor_sync(0xffffffffu, dwmax, off));
  float sc = lm * (fi / (1e-6f + dwmax));
#pragma unroll
  for (int off = 16; off; off >>= 1) sc = fmaxf(sc, __shfl_xor_sync(0xffffffffu, sc, off));
  if (c == 0) out_scores[i] = sc;
}

__global__ void k_out(const float* __restrict__ pcd_xyz, float* __restrict__ out) {
  int i = blockIdx.x*blockDim.x + threadIdx.x;
  if (i < N_PCD*3) out[i] = pcd_xyz[i];
}

extern "C" void kernel_launch(void* const* d_in, const int* in_sizes, int n_in,
                              void* d_out, int out_size) {
  (void)in_sizes; (void)n_in; (void)out_size;
  const float* pcd_xyz   = (const float*)d_in[0];
  const float* pcd_feat  = (const float*)d_in[1];
  const float* rgb_xyz   = (const float*)d_in[2];
  const float* rgb_feats = (const float*)d_in[3];
  const float* sa_W1 = (const float*)d_in[4];
  const float* sa_b1 = (const float*)d_in[5];
  const float* sa_W2 = (const float*)d_in[6];
  const float* sa_b2 = (const float*)d_in[7];
  const float* sa_W3 = (const float*)d_in[8];
  const float* sa_b3 = (const float*)d_in[9];
  const float* fp_W1 = (const float*)d_in[10];
  const float* fp_b1 = (const float*)d_in[11];
  const float* fp_W2 = (const float*)d_in[12];
  const float* fp_b2 = (const float*)d_in[13];
  float* out = (float*)d_out;
  float* out_scores = out + N_PCD*3;          // 15000..20000
  float* out_vf     = out + N_PCD*3 + N_PCD;  // 20000..180000

  static int smem_set = 0;
  if (!smem_set) {
    cudaFuncSetAttribute(k_fps7, cudaFuncAttributeMaxDynamicSharedMemorySize,
                         NTOT*(int)sizeof(float));
    smem_set = 1;
  }

  k_build<<<(NTOT+255)/256, 256>>>(pcd_xyz, rgb_xyz);           // 0
  k_cellscan<<<1, NCELL>>>();                                    // 1
  k_scatter<<<(NTOT+255)/256, 256>>>();                          // 2
  k_fps7<<<1, 1024, NTOT*sizeof(float)>>>();                     // 3  (ncu profiles this slot)
  k_transW<<<(78208+255)/256, 256>>>(sa_W1, sa_W2, sa_W3, fp_W1, fp_W2);
  { dim3 g((N_RGB+31)/32, 4), b(32, 8); k_transRGB<<<g, b>>>(rgb_feats); }
  k_ballq<<<(NA*32+255)/256, 256>>>(0);
  k_gather<<<NROWS, 192>>>(pcd_feat);
  k_gemm<<<NROWS/128, 256>>>(0, sa_b1, sa_b2, sa_b3);
  k_gemm<<<NROWS/128, 256>>>(1, sa_b1, sa_b2, sa_b3);
  k_gemm<<<NROWS/128, 256>>>(2, sa_b1, sa_b2, sa_b3);
  k_maxpool<<<NA, 128>>>();
  k_nn3<<<(N_PCD+255)/256, 256>>>();
  k_fp<<<N_PCD, 128>>>(pcd_feat, fp_b1, fp_b2, out_vf);
  k_ballq<<<(N_PCD*32+255)/256, 256>>>(1);
  k_det<<<N_PCD, 32>>>(out_scores);
  k_out<<<(N_PCD*3+255)/256, 256>>>(pcd_xyz, out);
}